// round 8
// baseline (speedup 1.0000x reference)
#include <cuda_runtime.h>

// Problem constants
#define BATCH 16
#define N1V 1024
#define N2V 4096
#define C1V 256
#define C2V 128
#define CINV 384
#define H1V 256
#define H2V 256
#define MCOLS (BATCH * N2V)   // 65536 columns of the "matrix" view

// ---------------- scratch (device globals; no runtime allocation) ----------
__device__ float g_X [CINV * MCOLS];   // [384, 65536]  interp||f2, channel-major
__device__ float g_Y1[H1V * MCOLS];    // [256, 65536]
__device__ float g_Y2[H2V * MCOLS];    // [256, 65536]
__device__ int   g_idx[MCOLS * 3];
__device__ float g_w  [MCOLS * 3];
__device__ float g_s1[H1V], g_t1[H1V], g_s2[H2V], g_t2[H2V];

// ---------------- 1) kNN-3 + inverse-distance weights ----------------------
// Distance arithmetic replicates the reference bit-for-bit:
//   pn  = (x*x + y*y) + z*z                (rn mul/add, left-assoc)
//   dot = fma(qz,pz, fma(qy,py, qx*px))    (fma-accumulated K=3, ascending)
//   d   = (qn + pn) + (-2)*dot             (rn ops)
// so near-tied candidates rank identically to the reference's top_k.
__global__ void knn_kernel(const float* __restrict__ p1,
                           const float* __restrict__ p2) {
    __shared__ float4 sp[N1V];                 // {x,y,z, |p|^2}
    const int b = blockIdx.y;
    const int t = threadIdx.x;

    const float* p1b = p1 + b * 3 * N1V;
    for (int i = t; i < N1V; i += 256) {
        float x = p1b[i], y = p1b[N1V + i], z = p1b[2 * N1V + i];
        float pn = __fadd_rn(__fadd_rn(__fmul_rn(x, x), __fmul_rn(y, y)),
                             __fmul_rn(z, z));
        sp[i] = make_float4(x, y, z, pn);
    }
    __syncthreads();

    const int n = blockIdx.x * 256 + t;
    const float* p2b = p2 + b * 3 * N2V;
    const float qx = p2b[n], qy = p2b[N2V + n], qz = p2b[2 * N2V + n];
    const float qn = __fadd_rn(__fadd_rn(__fmul_rn(qx, qx), __fmul_rn(qy, qy)),
                               __fmul_rn(qz, qz));

    float d0 = 3.4e38f, d1 = 3.4e38f, d2 = 3.4e38f;
    int   i0 = 0, i1 = 0, i2 = 0;
    #pragma unroll 4
    for (int i = 0; i < N1V; i++) {
        float4 p = sp[i];
        float dot = __fmaf_rn(qz, p.z, __fmaf_rn(qy, p.y, __fmul_rn(qx, p.x)));
        float d = __fadd_rn(__fadd_rn(qn, p.w), __fmul_rn(-2.0f, dot));
        if (d < d2) {
            if (d < d1) {
                d2 = d1; i2 = i1;
                if (d < d0) { d1 = d0; i1 = i0; d0 = d; i0 = i; }
                else        { d1 = d;  i1 = i; }
            } else { d2 = d; i2 = i; }
        }
    }
    // clamp, inverse-distance weights (exact reference sequence, rn division)
    float e0 = fmaxf(d0, 1e-10f);
    float e1 = fmaxf(d1, 1e-10f);
    float e2 = fmaxf(d2, 1e-10f);
    float v0 = __fdiv_rn(1.0f, e0);
    float v1 = __fdiv_rn(1.0f, e1);
    float v2 = __fdiv_rn(1.0f, e2);
    float s  = __fadd_rn(__fadd_rn(v0, v1), v2);

    const int base = (b * N2V + n) * 3;
    g_idx[base] = i0; g_idx[base + 1] = i1; g_idx[base + 2] = i2;
    g_w[base]     = __fdiv_rn(v0, s);
    g_w[base + 1] = __fdiv_rn(v1, s);
    g_w[base + 2] = __fdiv_rn(v2, s);
}

// ---------------- 2) interpolate C1 channels + copy f2 into X --------------
// X is channel-major [Cin, M]; block handles 256 consecutive j within one batch.
__global__ void interp_kernel(const float* __restrict__ f1,
                              const float* __restrict__ f2) {
    __shared__ float row[2][N1V];
    const int t = threadIdx.x;
    const int j = blockIdx.x * 256 + t;
    const int b = j >> 12;             // N2V = 4096
    const int n = j & (N2V - 1);

    const int base = j * 3;
    const int i0 = g_idx[base], i1 = g_idx[base + 1], i2 = g_idx[base + 2];
    const float w0 = g_w[base], w1 = g_w[base + 1], w2 = g_w[base + 2];

    const float4* f1b = (const float4*)(f1 + b * C1V * N1V);   // rows of 256 float4
    float4 nxt = f1b[t];               // c = 0
    int buf = 0;
    for (int c = 0; c < C1V; c++) {
        ((float4*)row[buf])[t] = nxt;
        __syncthreads();
        if (c + 1 < C1V) nxt = f1b[(c + 1) * 256 + t];
        // reference order: (g0*w0 + g1*w1) + g2*w2, rn mul/add
        float val = __fadd_rn(
            __fadd_rn(__fmul_rn(row[buf][i0], w0), __fmul_rn(row[buf][i1], w1)),
            __fmul_rn(row[buf][i2], w2));
        g_X[c * MCOLS + j] = val;
        buf ^= 1;
    }
    const float* f2b = f2 + b * C2V * N2V;
    #pragma unroll 4
    for (int c = 0; c < C2V; c++)
        g_X[(C1V + c) * MCOLS + j] = f2b[c * N2V + n];
}

// ---------------- 3/5) SGEMM: C[256 x 65536] = A[256 x K] * Bmat[K x 65536]
// PHASE2 fuses BN1+ReLU into the B-tile load (z = max(y*s+t, 0)).
template<int KDIM, bool PHASE2>
__global__ __launch_bounds__(256, 2)
void sgemm_kernel(const float* __restrict__ A) {
    const float* __restrict__ Bmat = PHASE2 ? g_Y1 : g_X;
    float* __restrict__ C          = PHASE2 ? g_Y2 : g_Y1;

    __shared__ float As[8][132];   // padded: conflict-free transposed stores
    __shared__ float Bs[8][128];

    const int tid = threadIdx.x;
    const int m0 = blockIdx.y * 128;
    const int n0 = blockIdx.x * 128;

    const int arow = tid >> 1;            // 0..127
    const int akp  = (tid & 1) * 4;       // 0 or 4
    const int bkk  = tid >> 5;            // 0..7
    const int bnn  = (tid & 31) * 4;      // 0..124

    const int ty = tid >> 4, tx = tid & 15;

    float acc[8][8];
    #pragma unroll
    for (int i = 0; i < 8; i++)
        #pragma unroll
        for (int jj = 0; jj < 8; jj++) acc[i][jj] = 0.f;

    for (int k0 = 0; k0 < KDIM; k0 += 8) {
        float4 av = *(const float4*)(A + (m0 + arow) * KDIM + k0 + akp);
        float4 bv = *(const float4*)(Bmat + (k0 + bkk) * MCOLS + n0 + bnn);
        if (PHASE2) {
            const float sc = g_s1[k0 + bkk];
            const float sh = g_t1[k0 + bkk];
            bv.x = fmaxf(__fmaf_rn(bv.x, sc, sh), 0.f);
            bv.y = fmaxf(__fmaf_rn(bv.y, sc, sh), 0.f);
            bv.z = fmaxf(__fmaf_rn(bv.z, sc, sh), 0.f);
            bv.w = fmaxf(__fmaf_rn(bv.w, sc, sh), 0.f);
        }
        __syncthreads();   // previous tile fully consumed
        As[akp + 0][arow] = av.x;
        As[akp + 1][arow] = av.y;
        As[akp + 2][arow] = av.z;
        As[akp + 3][arow] = av.w;
        *(float4*)&Bs[bkk][bnn] = bv;
        __syncthreads();

        #pragma unroll
        for (int kk = 0; kk < 8; kk++) {
            float4 a0 = *(const float4*)&As[kk][ty * 8];
            float4 a1 = *(const float4*)&As[kk][ty * 8 + 4];
            float4 b0 = *(const float4*)&Bs[kk][tx * 8];
            float4 b1 = *(const float4*)&Bs[kk][tx * 8 + 4];
            float a[8] = {a0.x, a0.y, a0.z, a0.w, a1.x, a1.y, a1.z, a1.w};
            float bb[8] = {b0.x, b0.y, b0.z, b0.w, b1.x, b1.y, b1.z, b1.w};
            #pragma unroll
            for (int i = 0; i < 8; i++)
                #pragma unroll
                for (int jj = 0; jj < 8; jj++)
                    acc[i][jj] = __fmaf_rn(a[i], bb[jj], acc[i][jj]);
        }
    }

    #pragma unroll
    for (int i = 0; i < 8; i++) {
        float* Cr = C + (m0 + ty * 8 + i) * MCOLS + n0 + tx * 8;
        *(float4*)(Cr)     = make_float4(acc[i][0], acc[i][1], acc[i][2], acc[i][3]);
        *(float4*)(Cr + 4) = make_float4(acc[i][4], acc[i][5], acc[i][6], acc[i][7]);
    }
}

// ---------------- 4/6) BN stats -> per-channel scale/shift -----------------
// PHASE: 1 reads g_Y1 -> (g_s1,g_t1); 2 reads g_Y2 -> (g_s2,g_t2)
template<int PHASE>
__global__ void bn_stats_kernel(const float* __restrict__ gamma,
                                const float* __restrict__ beta) {
    const float* __restrict__ Y = (PHASE == 1) ? g_Y1 : g_Y2;
    float* __restrict__ s = (PHASE == 1) ? g_s1 : g_s2;
    float* __restrict__ t = (PHASE == 1) ? g_t1 : g_t2;

    const int o = blockIdx.x, tid = threadIdx.x;
    const float* Yo = Y + o * MCOLS;
    double sum = 0.0, sq = 0.0;
    for (int j = tid; j < MCOLS; j += 256) {
        float v = Yo[j];
        sum += v;
        sq  += (double)v * (double)v;
    }
    #pragma unroll
    for (int off = 16; off; off >>= 1) {
        sum += __shfl_down_sync(0xffffffffu, sum, off);
        sq  += __shfl_down_sync(0xffffffffu, sq,  off);
    }
    __shared__ double ssum[8], ssq[8];
    if ((tid & 31) == 0) { ssum[tid >> 5] = sum; ssq[tid >> 5] = sq; }
    __syncthreads();
    if (tid == 0) {
        double S = 0.0, Q = 0.0;
        #pragma unroll
        for (int w = 0; w < 8; w++) { S += ssum[w]; Q += ssq[w]; }
        double mean = S / (double)MCOLS;
        double var  = Q / (double)MCOLS - mean * mean;
        float sc = gamma[o] * rsqrtf((float)var + 1e-3f);
        s[o] = sc;
        t[o] = beta[o] - (float)mean * sc;
    }
}

// ---------------- 7) BN2 + ReLU + permute to [B, H2, N2] -------------------
__global__ void output_kernel(float* __restrict__ out) {
    const int idx = blockIdx.x * 256 + threadIdx.x;   // b*H2*N2 + o*N2 + n
    const int n = idx & (N2V - 1);
    const int o = (idx >> 12) & 255;
    const int b = idx >> 20;
    float v = g_Y2[o * MCOLS + b * N2V + n];
    out[idx] = fmaxf(__fmaf_rn(v, g_s2[o], g_t2[o]), 0.f);
}

// ---------------- launcher --------------------------------------------------
extern "C" void kernel_launch(void* const* d_in, const int* in_sizes, int n_in,
                              void* d_out, int out_size) {
    (void)in_sizes; (void)n_in; (void)out_size;
    const float* points1 = (const float*)d_in[0];
    const float* points2 = (const float*)d_in[1];
    const float* feat1   = (const float*)d_in[2];
    const float* feat2   = (const float*)d_in[3];
    const float* W1      = (const float*)d_in[4];
    // d_in[5] = b1: bias cancels exactly under training-mode BatchNorm
    const float* g1      = (const float*)d_in[6];
    const float* beta1   = (const float*)d_in[7];
    const float* W2      = (const float*)d_in[8];
    // d_in[9] = b2: cancels as well
    const float* g2      = (const float*)d_in[10];
    const float* beta2   = (const float*)d_in[11];
    float* out = (float*)d_out;

    // 1) 3-NN + weights
    knn_kernel<<<dim3(N2V / 256, BATCH), 256>>>(points1, points2);
    // 2) interpolation + concat into X [384, 65536]
    interp_kernel<<<MCOLS / 256, 256>>>(feat1, feat2);
    // 3) Y1 = W1 * X
    sgemm_kernel<CINV, false><<<dim3(MCOLS / 128, H1V / 128), 256>>>(W1);
    // 4) BN1 stats -> scale/shift
    bn_stats_kernel<1><<<H1V, 256>>>(g1, beta1);
    // 5) Y2 = W2 * relu(bn1(Y1))   (BN+ReLU fused into B-load)
    sgemm_kernel<H1V, true><<<dim3(MCOLS / 128, H2V / 128), 256>>>(W2);
    // 6) BN2 stats
    bn_stats_kernel<2><<<H2V, 256>>>(g2, beta2);
    // 7) BN2 + ReLU + permute to output
    output_kernel<<<(BATCH * H2V * N2V) / 256, 256>>>(out);
}

// round 10
// speedup vs baseline: 1.3169x; 1.3169x over previous
#include <cuda_runtime.h>

// Problem constants
#define BATCH 16
#define N1V 1024
#define N2V 4096
#define C1V 256
#define C2V 128
#define CINV 384
#define H1V 256
#define H2V 256
#define MCOLS (BATCH * N2V)   // 65536 columns of the "matrix" view

// ---------------- scratch (device globals; no runtime allocation) ----------
__device__ float g_X [CINV * MCOLS];   // [384, 65536]  interp||f2, channel-major
__device__ float g_Y1[H1V * MCOLS];    // [256, 65536]
__device__ float g_Y2[H2V * MCOLS];    // [256, 65536]
__device__ int   g_idx[MCOLS * 3];
__device__ float g_w  [MCOLS * 3];
__device__ float g_s1[H1V], g_t1[H1V], g_s2[H2V], g_t2[H2V];
__device__ float g_sum1[H1V], g_sq1[H1V], g_sum2[H2V], g_sq2[H2V];

// ---------------- 0) zero the fused-stat accumulators ----------------------
__global__ void zero_stats_kernel() {
    const int t = threadIdx.x;           // 256 threads
    g_sum1[t] = 0.f; g_sq1[t] = 0.f;
    g_sum2[t] = 0.f; g_sq2[t] = 0.f;
}

// ---------------- 1) kNN-3 + inverse-distance weights ----------------------
// Distance arithmetic replicates the reference bit-for-bit:
//   pn  = (x*x + y*y) + z*z                (rn mul/add, left-assoc)
//   dot = fma(qz,pz, fma(qy,py, qx*px))    (fma-accumulated K=3, ascending)
//   d   = (qn + pn) + (-2)*dot             (rn ops)
__global__ void knn_kernel(const float* __restrict__ p1,
                           const float* __restrict__ p2) {
    __shared__ float4 sp[N1V];                 // {x,y,z, |p|^2}
    const int b = blockIdx.y;
    const int t = threadIdx.x;

    const float* p1b = p1 + b * 3 * N1V;
    for (int i = t; i < N1V; i += 256) {
        float x = p1b[i], y = p1b[N1V + i], z = p1b[2 * N1V + i];
        float pn = __fadd_rn(__fadd_rn(__fmul_rn(x, x), __fmul_rn(y, y)),
                             __fmul_rn(z, z));
        sp[i] = make_float4(x, y, z, pn);
    }
    __syncthreads();

    const int n = blockIdx.x * 256 + t;
    const float* p2b = p2 + b * 3 * N2V;
    const float qx = p2b[n], qy = p2b[N2V + n], qz = p2b[2 * N2V + n];
    const float qn = __fadd_rn(__fadd_rn(__fmul_rn(qx, qx), __fmul_rn(qy, qy)),
                               __fmul_rn(qz, qz));

    float d0 = 3.4e38f, d1 = 3.4e38f, d2 = 3.4e38f;
    int   i0 = 0, i1 = 0, i2 = 0;
    #pragma unroll 4
    for (int i = 0; i < N1V; i++) {
        float4 p = sp[i];
        float dot = __fmaf_rn(qz, p.z, __fmaf_rn(qy, p.y, __fmul_rn(qx, p.x)));
        float d = __fadd_rn(__fadd_rn(qn, p.w), __fmul_rn(-2.0f, dot));
        if (d < d2) {
            if (d < d1) {
                d2 = d1; i2 = i1;
                if (d < d0) { d1 = d0; i1 = i0; d0 = d; i0 = i; }
                else        { d1 = d;  i1 = i; }
            } else { d2 = d; i2 = i; }
        }
    }
    float e0 = fmaxf(d0, 1e-10f);
    float e1 = fmaxf(d1, 1e-10f);
    float e2 = fmaxf(d2, 1e-10f);
    float v0 = __fdiv_rn(1.0f, e0);
    float v1 = __fdiv_rn(1.0f, e1);
    float v2 = __fdiv_rn(1.0f, e2);
    float s  = __fadd_rn(__fadd_rn(v0, v1), v2);

    const int base = (b * N2V + n) * 3;
    g_idx[base] = i0; g_idx[base + 1] = i1; g_idx[base + 2] = i2;
    g_w[base]     = __fdiv_rn(v0, s);
    g_w[base + 1] = __fdiv_rn(v1, s);
    g_w[base + 2] = __fdiv_rn(v2, s);
}

// ---------------- 2) interpolate C1 channels + copy f2 into X --------------
__global__ void interp_kernel(const float* __restrict__ f1,
                              const float* __restrict__ f2) {
    __shared__ float row[2][N1V];
    const int t = threadIdx.x;
    const int j = blockIdx.x * 256 + t;
    const int b = j >> 12;             // N2V = 4096
    const int n = j & (N2V - 1);

    const int base = j * 3;
    const int i0 = g_idx[base], i1 = g_idx[base + 1], i2 = g_idx[base + 2];
    const float w0 = g_w[base], w1 = g_w[base + 1], w2 = g_w[base + 2];

    const float4* f1b = (const float4*)(f1 + b * C1V * N1V);   // rows of 256 float4
    float4 nxt = f1b[t];               // c = 0
    int buf = 0;
    for (int c = 0; c < C1V; c++) {
        ((float4*)row[buf])[t] = nxt;
        __syncthreads();
        if (c + 1 < C1V) nxt = f1b[(c + 1) * 256 + t];
        float val = __fadd_rn(
            __fadd_rn(__fmul_rn(row[buf][i0], w0), __fmul_rn(row[buf][i1], w1)),
            __fmul_rn(row[buf][i2], w2));
        g_X[c * MCOLS + j] = val;
        buf ^= 1;
    }
    const float* f2b = f2 + b * C2V * N2V;
    #pragma unroll 4
    for (int c = 0; c < C2V; c++)
        g_X[(C1V + c) * MCOLS + j] = f2b[c * N2V + n];
}

// ---------------- 3/5) SGEMM: C[256 x 65536] = A[256 x K] * Bmat[K x 65536]
// Double-buffered smem (1 sync per K-tile). PHASE2 fuses BN1+ReLU into the
// B-tile load. BN stats of the OUTPUT are fused into the epilogue:
// per-thread 8-col partials -> shfl-reduce over the 16-lane tx-group ->
// one atomicAdd pair per channel per block.
template<int KDIM, bool PHASE2>
__global__ __launch_bounds__(256, 2)
void sgemm_kernel(const float* __restrict__ A) {
    const float* __restrict__ Bmat = PHASE2 ? g_Y1 : g_X;
    float* __restrict__ C          = PHASE2 ? g_Y2 : g_Y1;
    float* __restrict__ gsum       = PHASE2 ? g_sum2 : g_sum1;
    float* __restrict__ gsq        = PHASE2 ? g_sq2  : g_sq1;

    __shared__ float As[2][8][132];   // padded: conflict-free transposed stores
    __shared__ float Bs[2][8][128];

    const int tid = threadIdx.x;
    const int m0 = blockIdx.y * 128;
    const int n0 = blockIdx.x * 128;

    const int arow = tid >> 1;            // 0..127
    const int akp  = (tid & 1) * 4;       // 0 or 4
    const int bkk  = tid >> 5;            // 0..7
    const int bnn  = (tid & 31) * 4;      // 0..124

    const int ty = tid >> 4, tx = tid & 15;

    float acc[8][8];
    #pragma unroll
    for (int i = 0; i < 8; i++)
        #pragma unroll
        for (int jj = 0; jj < 8; jj++) acc[i][jj] = 0.f;

    // ---- prologue: load K-tile 0 into buffer 0
    float4 av = *(const float4*)(A + (m0 + arow) * KDIM + akp);
    float4 bv = *(const float4*)(Bmat + bkk * MCOLS + n0 + bnn);
    if (PHASE2) {
        const float sc = g_s1[bkk];
        const float sh = g_t1[bkk];
        bv.x = fmaxf(__fmaf_rn(bv.x, sc, sh), 0.f);
        bv.y = fmaxf(__fmaf_rn(bv.y, sc, sh), 0.f);
        bv.z = fmaxf(__fmaf_rn(bv.z, sc, sh), 0.f);
        bv.w = fmaxf(__fmaf_rn(bv.w, sc, sh), 0.f);
    }
    As[0][akp + 0][arow] = av.x;
    As[0][akp + 1][arow] = av.y;
    As[0][akp + 2][arow] = av.z;
    As[0][akp + 3][arow] = av.w;
    *(float4*)&Bs[0][bkk][bnn] = bv;
    __syncthreads();

    int buf = 0;
    for (int k0 = 0; k0 < KDIM; k0 += 8) {
        const bool more = (k0 + 8 < KDIM);
        if (more) {
            av = *(const float4*)(A + (m0 + arow) * KDIM + k0 + 8 + akp);
            bv = *(const float4*)(Bmat + (k0 + 8 + bkk) * MCOLS + n0 + bnn);
            if (PHASE2) {
                const float sc = g_s1[k0 + 8 + bkk];
                const float sh = g_t1[k0 + 8 + bkk];
                bv.x = fmaxf(__fmaf_rn(bv.x, sc, sh), 0.f);
                bv.y = fmaxf(__fmaf_rn(bv.y, sc, sh), 0.f);
                bv.z = fmaxf(__fmaf_rn(bv.z, sc, sh), 0.f);
                bv.w = fmaxf(__fmaf_rn(bv.w, sc, sh), 0.f);
            }
        }

        #pragma unroll
        for (int kk = 0; kk < 8; kk++) {
            float4 a0 = *(const float4*)&As[buf][kk][ty * 8];
            float4 a1 = *(const float4*)&As[buf][kk][ty * 8 + 4];
            float4 b0 = *(const float4*)&Bs[buf][kk][tx * 8];
            float4 b1 = *(const float4*)&Bs[buf][kk][tx * 8 + 4];
            float a[8] = {a0.x, a0.y, a0.z, a0.w, a1.x, a1.y, a1.z, a1.w};
            float bb[8] = {b0.x, b0.y, b0.z, b0.w, b1.x, b1.y, b1.z, b1.w};
            #pragma unroll
            for (int i = 0; i < 8; i++)
                #pragma unroll
                for (int jj = 0; jj < 8; jj++)
                    acc[i][jj] = __fmaf_rn(a[i], bb[jj], acc[i][jj]);
        }

        if (more) {
            const int nb = buf ^ 1;
            As[nb][akp + 0][arow] = av.x;
            As[nb][akp + 1][arow] = av.y;
            As[nb][akp + 2][arow] = av.z;
            As[nb][akp + 3][arow] = av.w;
            *(float4*)&Bs[nb][bkk][bnn] = bv;
            __syncthreads();
        }
        buf ^= 1;
    }

    // ---- epilogue: store C tile + fused per-channel partial stats
    #pragma unroll
    for (int i = 0; i < 8; i++) {
        const int ch = m0 + ty * 8 + i;
        float* Cr = C + ch * MCOLS + n0 + tx * 8;
        *(float4*)(Cr)     = make_float4(acc[i][0], acc[i][1], acc[i][2], acc[i][3]);
        *(float4*)(Cr + 4) = make_float4(acc[i][4], acc[i][5], acc[i][6], acc[i][7]);

        float ps = 0.f, pq = 0.f;
        #pragma unroll
        for (int jj = 0; jj < 8; jj++) {
            ps = __fadd_rn(ps, acc[i][jj]);
            pq = __fmaf_rn(acc[i][jj], acc[i][jj], pq);
        }
        // reduce over the 16-lane tx-group (stays inside one half-warp)
        #pragma unroll
        for (int off = 8; off; off >>= 1) {
            ps += __shfl_xor_sync(0xffffffffu, ps, off);
            pq += __shfl_xor_sync(0xffffffffu, pq, off);
        }
        if (tx == 0) {
            atomicAdd(&gsum[ch], ps);
            atomicAdd(&gsq[ch], pq);
        }
    }
}

// ---------------- 4/6) finalize: (sum, sumsq) -> (scale, shift) ------------
template<int PHASE>
__global__ void finalize_kernel(const float* __restrict__ gamma,
                                const float* __restrict__ beta) {
    const int o = threadIdx.x;           // 256 threads, 1 block
    const float S = (PHASE == 1) ? g_sum1[o] : g_sum2[o];
    const float Q = (PHASE == 1) ? g_sq1[o]  : g_sq2[o];
    const float invM = 1.0f / (float)MCOLS;
    const float mean = S * invM;
    const float var  = __fmaf_rn(-mean, mean, Q * invM);
    const float sc   = gamma[o] * rsqrtf(var + 1e-3f);
    if (PHASE == 1) { g_s1[o] = sc; g_t1[o] = __fmaf_rn(-mean, sc, beta[o]); }
    else            { g_s2[o] = sc; g_t2[o] = __fmaf_rn(-mean, sc, beta[o]); }
}

// ---------------- 7) BN2 + ReLU + permute to [B, H2, N2] -------------------
__global__ void output_kernel(float* __restrict__ out) {
    const int idx = blockIdx.x * 256 + threadIdx.x;   // b*H2*N2 + o*N2 + n
    const int n = idx & (N2V - 1);
    const int o = (idx >> 12) & 255;
    const int b = idx >> 20;
    float v = g_Y2[o * MCOLS + b * N2V + n];
    out[idx] = fmaxf(__fmaf_rn(v, g_s2[o], g_t2[o]), 0.f);
}

// ---------------- launcher --------------------------------------------------
extern "C" void kernel_launch(void* const* d_in, const int* in_sizes, int n_in,
                              void* d_out, int out_size) {
    (void)in_sizes; (void)n_in; (void)out_size;
    const float* points1 = (const float*)d_in[0];
    const float* points2 = (const float*)d_in[1];
    const float* feat1   = (const float*)d_in[2];
    const float* feat2   = (const float*)d_in[3];
    const float* W1      = (const float*)d_in[4];
    // d_in[5] = b1: bias cancels exactly under training-mode BatchNorm
    const float* g1      = (const float*)d_in[6];
    const float* beta1   = (const float*)d_in[7];
    const float* W2      = (const float*)d_in[8];
    // d_in[9] = b2: cancels as well
    const float* g2      = (const float*)d_in[10];
    const float* beta2   = (const float*)d_in[11];
    float* out = (float*)d_out;

    // 0) zero fused-stat accumulators (graph replays must re-zero)
    zero_stats_kernel<<<1, 256>>>();
    // 1) 3-NN + weights
    knn_kernel<<<dim3(N2V / 256, BATCH), 256>>>(points1, points2);
    // 2) interpolation + concat into X [384, 65536]
    interp_kernel<<<MCOLS / 256, 256>>>(feat1, feat2);
    // 3) Y1 = W1 * X  (+ fused BN1 partial stats)
    sgemm_kernel<CINV, false><<<dim3(MCOLS / 128, H1V / 128), 256>>>(W1);
    // 4) finalize BN1 scale/shift
    finalize_kernel<1><<<1, 256>>>(g1, beta1);
    // 5) Y2 = W2 * relu(bn1(Y1))  (BN+ReLU fused into B-load; fused BN2 stats)
    sgemm_kernel<H1V, true><<<dim3(MCOLS / 128, H2V / 128), 256>>>(W2);
    // 6) finalize BN2 scale/shift
    finalize_kernel<2><<<1, 256>>>(g2, beta2);
    // 7) BN2 + ReLU + permute to output
    output_kernel<<<(BATCH * H2V * N2V) / 256, 256>>>(out);
}